// round 2
// baseline (speedup 1.0000x reference)
#include <cuda_runtime.h>
#include <cuda_bf16.h>

// ============================================================================
// Problem constants
// ============================================================================
#define T_STEPS 128
#define BS      64
#define NP      64      // particles
#define H       256
#define OUTD    64
#define M_ROWS  (BS*NP)             // 4096 rows per state GEMM
#define STATE_ELEMS (BS*NP*H)       // 1048576
#define GUM_TOTAL   (NP*BS*NP)      // 262144

// ============================================================================
// Device scratch (static allocations only — no cudaMalloc allowed)
// ============================================================================
__device__ float g_x[STATE_ELEMS];        // particle state x  [BS*NP, H]
__device__ float g_h[STATE_ELEMS];        // h (post tanh+noise)
__device__ float g_act[STATE_ELEMS];      // FFN hidden activation
__device__ float g_noise[STATE_ELEMS];    // per-step scaled normal noise
__device__ float g_proj[T_STEPS*BS*H];    // u @ W_ih^T + b_ih for all t
__device__ float g_lp[BS*NP];             // log-prob per (b, n)
__device__ float g_sxstd[H];              // sqrt(sigma_x_diag)
__device__ unsigned g_keybits[512];       // split-foldlike keys: key j = ([2j],[2j+1])
__device__ unsigned g_x0key[2];           // fold_in(key, 0)

// ============================================================================
// JAX Threefry-2x32 (exact replication)
// ============================================================================
__device__ __forceinline__ unsigned rotl32(unsigned v, int d) {
    return __funnelshift_l(v, v, d);
}

__device__ __forceinline__ void threefry2x32(unsigned k0, unsigned k1,
                                             unsigned x, unsigned y,
                                             unsigned &o0, unsigned &o1) {
    unsigned k2 = k0 ^ k1 ^ 0x1BD11BDAu;
    x += k0; y += k1;
#define TF_R(r) { x += y; y = rotl32(y, (r)); y ^= x; }
    TF_R(13) TF_R(15) TF_R(26) TF_R(6)
    x += k1; y += k2 + 1u;
    TF_R(17) TF_R(29) TF_R(16) TF_R(24)
    x += k2; y += k0 + 2u;
    TF_R(13) TF_R(15) TF_R(26) TF_R(6)
    x += k0; y += k1 + 3u;
    TF_R(17) TF_R(29) TF_R(16) TF_R(24)
    x += k1; y += k2 + 4u;
    TF_R(13) TF_R(15) TF_R(26) TF_R(6)
    x += k2; y += k0 + 5u;
#undef TF_R
    o0 = x; o1 = y;
}

// Partitionable-mode random_bits: one threefry per element, counter (0, i),
// 32-bit output = X ^ Y lanes.
__device__ __forceinline__ unsigned jax_random_bits32(unsigned k0, unsigned k1,
                                                      unsigned i) {
    unsigned a, b;
    threefry2x32(k0, k1, 0u, i, a, b);
    return a ^ b;
}

// ============================================================================
// JAX uniform / normal / gumbel from raw bits
// ============================================================================
__device__ __forceinline__ float bits_to_unit(unsigned b) {
    // bitcast(bits>>9 | 0x3f800000) - 1.0  ->  [0, 1)
    return __uint_as_float((b >> 9) | 0x3f800000u) - 1.0f;
}

// XLA ErfInv32 (Giles 2012 polynomial) — matches lax.erf_inv on f32
__device__ __forceinline__ float erfinv_xla(float x) {
    float w = -log1pf(-x * x);
    float p;
    if (w < 5.0f) {
        w -= 2.5f;
        p = 2.81022636e-08f;
        p = fmaf(p, w, 3.43273939e-07f);
        p = fmaf(p, w, -3.5233877e-06f);
        p = fmaf(p, w, -4.39150654e-06f);
        p = fmaf(p, w, 0.00021858087f);
        p = fmaf(p, w, -0.00125372503f);
        p = fmaf(p, w, -0.00417768164f);
        p = fmaf(p, w, 0.246640727f);
        p = fmaf(p, w, 1.50140941f);
    } else {
        w = sqrtf(w) - 3.0f;
        p = -0.000200214257f;
        p = fmaf(p, w, 0.000100950558f);
        p = fmaf(p, w, 0.00134934322f);
        p = fmaf(p, w, -0.00367342844f);
        p = fmaf(p, w, 0.00573950773f);
        p = fmaf(p, w, -0.0076224613f);
        p = fmaf(p, w, 0.00943887047f);
        p = fmaf(p, w, 1.00167406f);
        p = fmaf(p, w, 2.83297682f);
    }
    return p * x;
}

__device__ __forceinline__ float jax_normal_from_bits(unsigned b) {
    float f = bits_to_unit(b);
    // uniform(lo=nextafter(-1,0), hi=1):  (hi-lo) rounds to 2.0f in fp32
    float u = f * 2.0f + (-0.99999994f);
    return 1.41421354f * erfinv_xla(u);   // float32(sqrt(2)) * erfinv
}

__device__ __forceinline__ float jax_gumbel_from_bits(unsigned b) {
    float f = bits_to_unit(b);
    // uniform(minval=tiny, maxval=1): (1-tiny) == 1.0f in fp32
    float u = fmaxf(1.17549435e-38f, f + 1.17549435e-38f);
    return -logf(-logf(u));
}

// ============================================================================
// Key / scale preparation (single tiny kernel)
// ============================================================================
__global__ void prep_kernel(const float* __restrict__ sx) {
    int i = threadIdx.x;   // 256 threads
    if (i < H) g_sxstd[i] = sqrtf(sx[i]);
    // base key jax.random.key(42) = (0, 42)
    // split base = fold_in(key, 1) = threefry(key, (0,1))
    unsigned sb0, sb1;
    threefry2x32(0u, 42u, 0u, 1u, sb0, sb1);
    // split-foldlike (partitionable): key i = (X, Y) of threefry(sb, (0, i))
    unsigned o0, o1;
    threefry2x32(sb0, sb1, 0u, (unsigned)i, o0, o1);
    g_keybits[2*i]     = o0;   // X lane
    g_keybits[2*i + 1] = o1;   // Y lane
    if (i == 0) {
        unsigned a, b;
        threefry2x32(0u, 42u, 0u, 0u, a, b);  // fold_in(key, 0)
        g_x0key[0] = a; g_x0key[1] = b;
    }
}

// ============================================================================
// Noise generation kernels (partitionable random_bits: 1 threefry/elem)
// ============================================================================
__global__ void x0_kernel() {
    int i = blockIdx.x * blockDim.x + threadIdx.x;   // < 1048576
    unsigned bits = jax_random_bits32(g_x0key[0], g_x0key[1], (unsigned)i);
    g_x[i] = jax_normal_from_bits(bits);
}

__global__ void noise_kernel(int t) {
    int i = blockIdx.x * blockDim.x + threadIdx.x;   // < 1048576
    unsigned k0 = g_keybits[4*t];     // split key index 2t
    unsigned k1 = g_keybits[4*t + 1];
    unsigned bits = jax_random_bits32(k0, k1, (unsigned)i);
    float s = g_sxstd[i & (H - 1)];
    g_noise[i] = jax_normal_from_bits(bits) * s;
}

// ============================================================================
// Tiled fp32 GEMM core: C_tile[64x64] = A[M,K] * B, 256 threads, 4x4/thread
// BT = true : B is [N,K] row-major (C = A * B^T)
// BT = false: B is [K,N] row-major (C = A * B)
// ============================================================================
template<bool BT>
__device__ __forceinline__ void gemm_tile(const float* __restrict__ A,
                                          const float* __restrict__ B,
                                          int K, int ldbn, float acc[4][4]) {
    __shared__ __align__(16) float As[16][68];
    __shared__ __align__(16) float Bs[16][68];
    int tid = threadIdx.x;
    int tx = tid & 15, ty = tid >> 4;
    int arow = tid >> 2;            // 0..63
    int akq  = (tid & 3) << 2;      // 0,4,8,12
    const float* Ap = A + ((size_t)(blockIdx.x * 64 + arow)) * K + akq;
    const float* Bp;
    int bk = 0, bnq = 0;
    if (BT) {
        Bp = B + ((size_t)(blockIdx.y * 64 + arow)) * K + akq;
    } else {
        bk  = tid >> 4;             // 0..15
        bnq = (tid & 15) << 2;      // 0..60
        Bp = B + (size_t)bk * ldbn + blockIdx.y * 64 + bnq;
    }
    for (int k0 = 0; k0 < K; k0 += 16) {
        float4 av = *(const float4*)(Ap + k0);
        float4 bv;
        if (BT) bv = *(const float4*)(Bp + k0);
        else    bv = *(const float4*)(Bp + (size_t)k0 * ldbn);
        __syncthreads();
        As[akq+0][arow] = av.x; As[akq+1][arow] = av.y;
        As[akq+2][arow] = av.z; As[akq+3][arow] = av.w;
        if (BT) {
            Bs[akq+0][arow] = bv.x; Bs[akq+1][arow] = bv.y;
            Bs[akq+2][arow] = bv.z; Bs[akq+3][arow] = bv.w;
        } else {
            *(float4*)&Bs[bk][bnq] = bv;
        }
        __syncthreads();
#pragma unroll
        for (int kk = 0; kk < 16; kk++) {
            float4 a = *(const float4*)&As[kk][ty << 2];
            float4 b = *(const float4*)&Bs[kk][tx << 2];
            acc[0][0] = fmaf(a.x, b.x, acc[0][0]);
            acc[0][1] = fmaf(a.x, b.y, acc[0][1]);
            acc[0][2] = fmaf(a.x, b.z, acc[0][2]);
            acc[0][3] = fmaf(a.x, b.w, acc[0][3]);
            acc[1][0] = fmaf(a.y, b.x, acc[1][0]);
            acc[1][1] = fmaf(a.y, b.y, acc[1][1]);
            acc[1][2] = fmaf(a.y, b.z, acc[1][2]);
            acc[1][3] = fmaf(a.y, b.w, acc[1][3]);
            acc[2][0] = fmaf(a.z, b.x, acc[2][0]);
            acc[2][1] = fmaf(a.z, b.y, acc[2][1]);
            acc[2][2] = fmaf(a.z, b.z, acc[2][2]);
            acc[2][3] = fmaf(a.z, b.w, acc[2][3]);
            acc[3][0] = fmaf(a.w, b.x, acc[3][0]);
            acc[3][1] = fmaf(a.w, b.y, acc[3][1]);
            acc[3][2] = fmaf(a.w, b.z, acc[3][2]);
            acc[3][3] = fmaf(a.w, b.w, acc[3][3]);
        }
    }
}

// ============================================================================
// GEMM epilogue kernels
// ============================================================================
// proj[t,b,:] = u[t,b,:] @ W_ih^T + b_ih  (all timesteps at once; M = T*BS)
__global__ void proj_kernel(const float* __restrict__ u,
                            const float* __restrict__ W_ih,
                            const float* __restrict__ b_ih) {
    float acc[4][4] = {};
    gemm_tile<true>(u, W_ih, H, 0, acc);
    int tx = threadIdx.x & 15, ty = threadIdx.x >> 4;
    int row0 = blockIdx.x * 64 + ty * 4;
    int col0 = blockIdx.y * 64 + tx * 4;
#pragma unroll
    for (int i = 0; i < 4; i++)
#pragma unroll
        for (int j = 0; j < 4; j++) {
            int c = col0 + j;
            g_proj[(size_t)(row0 + i) * H + c] = acc[i][j] + b_ih[c];
        }
}

// h = tanh(proj + x @ W_hh^T + b_hh) + noise
__global__ void h_kernel(const float* __restrict__ W_hh,
                         const float* __restrict__ b_hh, int t) {
    float acc[4][4] = {};
    gemm_tile<true>(g_x, W_hh, H, 0, acc);
    int tx = threadIdx.x & 15, ty = threadIdx.x >> 4;
    int row0 = blockIdx.x * 64 + ty * 4;
    int col0 = blockIdx.y * 64 + tx * 4;
#pragma unroll
    for (int i = 0; i < 4; i++) {
        int m = row0 + i;
        int b = m >> 6;
#pragma unroll
        for (int j = 0; j < 4; j++) {
            int c = col0 + j;
            float pre = (g_proj[((size_t)t * BS + b) * H + c] + acc[i][j]) + b_hh[c];
            g_h[(size_t)m * H + c] = tanhf(pre) + g_noise[(size_t)m * H + c];
        }
    }
}

// act = relu(h @ W1 + b1)
__global__ void ffn_kernel(const float* __restrict__ W1,
                           const float* __restrict__ b1) {
    float acc[4][4] = {};
    gemm_tile<false>(g_h, W1, H, H, acc);
    int tx = threadIdx.x & 15, ty = threadIdx.x >> 4;
    int row0 = blockIdx.x * 64 + ty * 4;
    int col0 = blockIdx.y * 64 + tx * 4;
#pragma unroll
    for (int i = 0; i < 4; i++)
#pragma unroll
        for (int j = 0; j < 4; j++) {
            int c = col0 + j;
            g_act[(size_t)(row0 + i) * H + c] = fmaxf(acc[i][j] + b1[c], 0.0f);
        }
}

// y_hat = act @ W2 + b2 -> out[t]; lp[b,n] = -0.5 * sum((y_hat-y)^2 / sigma_y)
__global__ void out_kernel(const float* __restrict__ W2,
                           const float* __restrict__ b2,
                           const float* __restrict__ y,
                           const float* __restrict__ sy,
                           float* __restrict__ out, int t) {
    float acc[4][4] = {};
    gemm_tile<false>(g_act, W2, H, OUTD, acc);
    int tx = threadIdx.x & 15, ty = threadIdx.x >> 4;
    int row0 = blockIdx.x * 64 + ty * 4;
    int col0 = tx * 4;   // N = 64 -> single column block
    float sums[4] = {0.f, 0.f, 0.f, 0.f};
#pragma unroll
    for (int i = 0; i < 4; i++) {
        int m = row0 + i;
        int b = m >> 6;
#pragma unroll
        for (int j = 0; j < 4; j++) {
            int c = col0 + j;
            float v = acc[i][j] + b2[c];
            out[(((size_t)t * M_ROWS) + m) * OUTD + c] = v;
            float d = v - y[(((size_t)t * BS) + b) * OUTD + c];
            sums[i] += d * d / sy[c];
        }
    }
#pragma unroll
    for (int i = 0; i < 4; i++) {
        float s = sums[i];
#pragma unroll
        for (int off = 8; off; off >>= 1)
            s += __shfl_xor_sync(0xffffffffu, s, off, 16);
        if (tx == 0) g_lp[row0 + i] = -0.5f * s;
    }
}

// ============================================================================
// Resampling: logw = log_softmax(lp); I[b,r] = argmax_n(gumbel + logw);
// x_new[b,r,:] = h[b, I[b,r], :]
// ============================================================================
__global__ void res_kernel(int t) {
    __shared__ float lp_s[NP];
    __shared__ float logw_s[NP];
    __shared__ float v_s[NP * NP];   // [r][n], 16 KB
    __shared__ int   I_s[NP];
    __shared__ float red_s[2];
    int b = blockIdx.x;
    int tid = threadIdx.x;

    if (tid < NP) lp_s[tid] = g_lp[b * NP + tid];
    __syncthreads();
    if (tid == 0) {
        float m = lp_s[0];
        for (int n = 1; n < NP; n++) m = fmaxf(m, lp_s[n]);
        float s = 0.0f;
        for (int n = 0; n < NP; n++) s += expf(lp_s[n] - m);
        red_s[0] = m; red_s[1] = logf(s);
    }
    __syncthreads();
    if (tid < NP) logw_s[tid] = (lp_s[tid] - red_s[0]) - red_s[1];
    __syncthreads();

    unsigned ck0 = g_keybits[4*t + 2];   // split key index 2t+1
    unsigned ck1 = g_keybits[4*t + 3];
    // gumbel flat index over (N, bs, N): p = (r*BS + b)*NP + n
    for (int l = tid; l < NP * NP; l += 256) {
        int r = l >> 6;          // 0..63
        int n = l & 63;
        unsigned p = (unsigned)(4096 * r + 64 * b + n);
        unsigned bits = jax_random_bits32(ck0, ck1, p);
        v_s[r * 64 + n] = jax_gumbel_from_bits(bits) + logw_s[n];
    }
    __syncthreads();

    int warp = tid >> 5, lane = tid & 31;
    for (int r = warp; r < NP; r += 8) {
        float v1 = v_s[r * 64 + lane];
        float v2 = v_s[r * 64 + 32 + lane];
        float val; int idx;
        if (v2 > v1) { val = v2; idx = lane + 32; }
        else         { val = v1; idx = lane; }
#pragma unroll
        for (int off = 16; off; off >>= 1) {
            float ov = __shfl_down_sync(0xffffffffu, val, off);
            int   oi = __shfl_down_sync(0xffffffffu, idx, off);
            if (ov > val || (ov == val && oi < idx)) { val = ov; idx = oi; }
        }
        if (lane == 0) I_s[r] = idx;   // jnp.argmax: first occurrence on tie
    }
    __syncthreads();

    // gather x_new = h[b, I, :], float4 copies
    const float4* hsrc = (const float4*)g_h;
    float4*       xdst = (float4*)g_x;
#pragma unroll
    for (int j = 0; j < 16; j++) {
        int lin = tid + 256 * j;       // 0..4095
        int r = lin >> 6;
        int c = lin & 63;              // float4 index within row (64 per row)
        int src = I_s[r];
        xdst[((size_t)(b * NP + r)) * 64 + c] =
            hsrc[((size_t)(b * NP + src)) * 64 + c];
    }
}

// ============================================================================
// Launch
// ============================================================================
extern "C" void kernel_launch(void* const* d_in, const int* in_sizes, int n_in,
                              void* d_out, int out_size) {
    const float* u    = (const float*)d_in[0];
    const float* y    = (const float*)d_in[1];
    const float* W_ih = (const float*)d_in[2];
    const float* W_hh = (const float*)d_in[3];
    const float* b_ih = (const float*)d_in[4];
    const float* b_hh = (const float*)d_in[5];
    const float* W1   = (const float*)d_in[6];
    const float* b1   = (const float*)d_in[7];
    const float* W2   = (const float*)d_in[8];
    const float* b2   = (const float*)d_in[9];
    const float* sx   = (const float*)d_in[10];
    const float* sy   = (const float*)d_in[11];
    float* out = (float*)d_out;
    (void)in_sizes; (void)n_in; (void)out_size;

    prep_kernel<<<1, 256>>>(sx);
    x0_kernel<<<STATE_ELEMS / 256, 256>>>();
    // u projection for ALL timesteps: M = T*BS = 8192 rows
    proj_kernel<<<dim3(T_STEPS * BS / 64, H / 64), 256>>>(u, W_ih, b_ih);

    for (int t = 0; t < T_STEPS; t++) {
        noise_kernel<<<STATE_ELEMS / 256, 256>>>(t);
        h_kernel<<<dim3(M_ROWS / 64, H / 64), 256>>>(W_hh, b_hh, t);
        ffn_kernel<<<dim3(M_ROWS / 64, H / 64), 256>>>(W1, b1);
        out_kernel<<<dim3(M_ROWS / 64, 1), 256>>>(W2, b2, y, sy, out, t);
        res_kernel<<<BS, 256>>>(t);
    }
}